// round 7
// baseline (speedup 1.0000x reference)
#include <cuda_runtime.h>
#include <math.h>

#define SEQ      65536
#define FEAT     512
#define G        1024         // total blocks
#define TPB      256
#define NW       8
#define RPB      64           // gemv rows per block
#define NB       128          // scan segments (blocks 0..127)
#define EPS      512          // elements per scan segment
#define THRES1   0.8f
#define THRES_UP 0.5f
#define MAXF     60

__device__ float g_a[SEQ];

// cross-block exchange records + flags (epoch-tagged, never reset)
__device__ float2   g_A[NB], g_B[NB], g_C[NB];
__device__ float4   g_D[NB];            // loss, cnt, lf, lv
__device__ int      g_didx[NB];
__device__ float    g_dypre[NB];
__device__ unsigned g_fA[NB], g_fB[NB], g_fC[NB], g_fD[NB];
__device__ unsigned g_fG[G];            // per-block gemv completion
__device__ unsigned g_epoch = 0, g_done = 0;

__device__ __forceinline__ void st_rel(unsigned* p, unsigned v) {
    asm volatile("st.release.gpu.u32 [%0], %1;" :: "l"(p), "r"(v) : "memory");
}
__device__ __forceinline__ unsigned ld_acq(const unsigned* p) {
    unsigned v;
    asm volatile("ld.acquire.gpu.u32 %0, [%1];" : "=r"(v) : "l"(p) : "memory");
    return v;
}

// OP 0: segmented max  | OP 1: linear | OP 2: last-set select
// comb: t2 := t2 ∘ t1 (t1 earlier, t2 later)
template<int OP>
__device__ __forceinline__ void comb(float f1, float v1, float& f2, float& v2) {
    if (OP == 0) { v2 = (f2 != 0.f) ? fmaxf(v1, v2) : v2; f2 = f1 * f2; }
    if (OP == 1) { v2 = f2 * v1 + v2;                      f2 = f1 * f2; }
    if (OP == 2) { v2 = (f2 != 0.f) ? v1 : v2;             f2 = f1 * f2; }
}

// Block-wide (256 threads) EXCLUSIVE scan; returns exclusive prefix + total.
template<int OP>
__device__ void blk_scan_excl(float f, float v, float idv,
                              float& fex, float& vex,
                              float& ftot, float& vtot,
                              float* sf, float* sv) {
    int lane = threadIdx.x & 31, w = threadIdx.x >> 5;
#pragma unroll
    for (int d = 1; d < 32; d <<= 1) {
        float ff = __shfl_up_sync(0xffffffffu, f, d);
        float vv = __shfl_up_sync(0xffffffffu, v, d);
        if (lane >= d) comb<OP>(ff, vv, f, v);
    }
    __syncthreads();
    if (lane == 31) { sf[w] = f; sv[w] = v; }
    __syncthreads();
    float pf = 1.f, pv = idv;
    for (int i = 0; i < w; i++) {
        float cf = sf[i], cv = sv[i];
        comb<OP>(pf, pv, cf, cv);
        pf = cf; pv = cv;
    }
    float tf = 1.f, tv = idv;
#pragma unroll
    for (int i = 0; i < NW; i++) {
        float cf = sf[i], cv = sv[i];
        comb<OP>(tf, tv, cf, cv);
        tf = cf; tv = cv;
    }
    ftot = tf; vtot = tv;
    float lf = __shfl_up_sync(0xffffffffu, f, 1);
    float lv = __shfl_up_sync(0xffffffffu, v, 1);
    if (lane == 0) { lf = 1.f; lv = idv; }
    comb<OP>(pf, pv, lf, lv);
    fex = lf; vex = lv;
}

// TRUE lookback over NB=128 records: thread tid polls record tid iff tid < b.
// Threads >= b (incl. 128..255) contribute identity. tid==b publishes carry.
template<int OP>
__device__ void lookback_earlier(const float2* gd, const unsigned* gf,
                                 unsigned expv, float idv,
                                 float* sf, float* sv, float* s_c) {
    int tid = threadIdx.x, lane = tid & 31, w = tid >> 5;
    int b = blockIdx.x;
    float f = 1.f, v = idv;
    if (tid < b) {
        while (ld_acq(&gf[tid]) != expv) { }
        float2 d = gd[tid];
        f = d.x; v = d.y;
    }
#pragma unroll
    for (int dd = 1; dd < 32; dd <<= 1) {
        float ff = __shfl_up_sync(0xffffffffu, f, dd);
        float vv = __shfl_up_sync(0xffffffffu, v, dd);
        if (lane >= dd) comb<OP>(ff, vv, f, v);
    }
    __syncthreads();
    if (lane == 31) { sf[w] = f; sv[w] = v; }
    __syncthreads();
    float pf = 1.f, pv = idv;
    for (int i = 0; i < w; i++) {
        float cf = sf[i], cv = sv[i];
        comb<OP>(pf, pv, cf, cv);
        pf = cf; pv = cv;
    }
    float lf = __shfl_up_sync(0xffffffffu, f, 1);
    float lv = __shfl_up_sync(0xffffffffu, v, 1);
    if (lane == 0) { lf = 1.f; lv = idv; }
    comb<OP>(pf, pv, lf, lv);
    if (tid == b) { s_c[0] = lf; s_c[1] = lv; }
    __syncthreads();
}

__device__ __forceinline__ void resolve_fall(float lc, float ypre, int gidx,
                                             const float* __restrict__ th2,
                                             float& loss, float& cnt) {
    bool isneg = (lc == -1.f);
    bool nz    = (lc != 0.f);
    if (!isneg && nz) { loss += lc; cnt += 1.f; }            // * R (R=1)
    else if (!isneg && !nz && ypre >= THRES1) {
        float t2 = th2[gidx < MAXF - 1 ? gidx : MAXF - 1];
        float d = ypre - t2;
        loss += d * d; cnt += 1.f;
    }
}

// ---------------------------------------------------------------------------
// ONE kernel: every block does 64 gemv rows; blocks 0..127 also run one scan
// segment overlapped with the grid-wide gemv.
// ---------------------------------------------------------------------------
__global__ void __launch_bounds__(TPB)
k_tgnn(const float* __restrict__ h, const float* __restrict__ W,
       const float* __restrict__ bptr,
       const float* __restrict__ up, const float* __restrict__ lab,
       const float* __restrict__ th2, float* __restrict__ out,
       int out_size) {
    __shared__ float4 sW[FEAT / 4];
    __shared__ float  sf[NW], sv[NW];
    __shared__ float  s_c[2];
    __shared__ int    s_didx;
    __shared__ float  s_dypre;

    const int b    = blockIdx.x;
    const int tid  = threadIdx.x;
    const int lane = tid & 31;
    const int w    = tid >> 5;
    const bool is_scan = (b < NB);

    const unsigned e    = *(volatile unsigned*)&g_epoch;
    const unsigned expv = e + 1u;

    if (tid < FEAT / 4) sW[tid] = ((const float4*)W)[tid];
    __syncthreads();

    // per-thread scan registers (2 consecutive elements, float2)
    float ue[2], uh[2];
    float fexA = 1.f, vexA = -1.f;
    const int gi = b * TPB + tid;            // float2 index within segment

    // ============ Phase A (scan blocks): up_hat BEFORE gemv ================
    if (is_scan) {
        float2 u2 = ((const float2*)up)[gi];
        ue[0] = u2.x; ue[1] = u2.y;
        ((float2*)(out + 2 * SEQ))[gi] = u2; // u_pred copy output

        float f = 1.f, v = -1.f;
#pragma unroll
        for (int ee = 0; ee < 2; ee++) {
            if (ue[ee] >= THRES_UP) v = fmaxf(v, ue[ee]);
            else { f = 0.f; v = -1.f; }
        }
        float ftA, vtA;
        blk_scan_excl<0>(f, v, -1.f, fexA, vexA, ftA, vtA, sf, sv);
        if (tid == 0) {
            g_A[b] = make_float2(ftA, vtA);
            st_rel(&g_fA[b], expv);
        }
        lookback_earlier<0>(g_A, g_fA, expv, -1.f, sf, sv, s_c);
        float m = (fexA != 0.f) ? fmaxf(s_c[1], vexA) : vexA;
#pragma unroll
        for (int ee = 0; ee < 2; ee++) {
            if (ue[ee] >= THRES_UP) { m = fmaxf(m, ue[ee]); uh[ee] = m; }
            else                    { m = -1.f;             uh[ee] = ue[ee]; }
        }
        ((float2*)(out + 3 * SEQ))[gi] = make_float2(uh[0], uh[1]);
    }

    // ============ GEMV: 64 rows per block, 8 rows per warp =================
    {
        const float bias = __ldg(bptr);
        const int row0 = b * RPB + w * 8;
#pragma unroll 2
        for (int r = 0; r < 8; r++) {
            const float4* hr = (const float4*)(h + (size_t)(row0 + r) * FEAT);
            float s = 0.f;
#pragma unroll
            for (int k = 0; k < 4; k++) {
                float4 hv = hr[lane + 32 * k];
                float4 wv = sW[lane + 32 * k];
                s += hv.x * wv.x + hv.y * wv.y + hv.z * wv.z + hv.w * wv.w;
            }
#pragma unroll
            for (int d = 16; d; d >>= 1) s += __shfl_down_sync(0xffffffffu, s, d);
            if (lane == 0) g_a[row0 + r] = 1.f / (1.f + __expf(-(s + bias)));
        }
    }
    __syncthreads();
    if (tid == 0) st_rel(&g_fG[b], expv);

    if (!is_scan) {
        // epoch bookkeeping and exit
        if (tid == 0) {
            unsigned prev = atomicAdd(&g_done, 1u);
            if (prev == (unsigned)(G - 1)) {
                g_done = 0;
                *(volatile unsigned*)&g_epoch = e + 1u;
            }
        }
        return;
    }

    // ============ Wait for the 8 gemv blocks covering this segment =========
    if (tid < 8) {
        while (ld_acq(&g_fG[8 * b + tid]) != expv) { }
    }
    __syncthreads();

    // ============ Phase B: alpha (linear scan) ==============================
    float2 a2 = ((const float2*)g_a)[gi];
    float ae[2] = {a2.x, a2.y};
    float p = 1.f, q = 0.f;
#pragma unroll
    for (int ee = 0; ee < 2; ee++) {
        q = uh[ee] * q + (1.f - uh[ee]) * ae[ee];
        p = uh[ee] * p;
    }
    float fexB, vexB, ftB, vtB;
    blk_scan_excl<1>(p, q, 0.f, fexB, vexB, ftB, vtB, sf, sv);
    if (tid == 0) {
        g_B[b] = make_float2(ftB, vtB);
        st_rel(&g_fB[b], expv);
    }
    lookback_earlier<1>(g_B, g_fB, expv, 0.f, sf, sv, s_c);
    float al = fexB * s_c[1] + vexB;

    float alv[2];
#pragma unroll
    for (int ee = 0; ee < 2; ee++) {
        al = uh[ee] * al + (1.f - uh[ee]) * ae[ee];
        alv[ee] = al;
    }
    ((float2*)(out + SEQ))[gi] = make_float2(alv[0], alv[1]);

    // ============ Phase C: y (linear scan with resets) ======================
    float yp = 1.f, yq = 0.f;
#pragma unroll
    for (int ee = 0; ee < 2; ee++) {
        float A = 0.f, B = 0.f;
        if (uh[ee] >= THRES_UP) { A = 1.f - alv[ee]; B = alv[ee] * uh[ee]; }
        yq = A * yq + B;
        yp = A * yp;
    }
    float fexC, vexC, ftC, vtC;
    blk_scan_excl<1>(yp, yq, 0.f, fexC, vexC, ftC, vtC, sf, sv);
    if (tid == 0) {
        g_C[b] = make_float2(ftC, vtC);
        st_rel(&g_fC[b], expv);
    }
    lookback_earlier<1>(g_C, g_fC, expv, 0.f, sf, sv, s_c);
    float y = fexC * s_c[1] + vexC;          // y entering this thread's chunk

    // ============ Phase D: y values + l_c / loss / cnt ======================
    float2 l2 = ((const float2*)lab)[gi];
    float le[2] = {l2.x, l2.y};

    int   gbase = gi * 2;
    float uprev = (gbase == 0) ? 0.f : up[gbase - 1];

    float lcf = 1.f, lcv = 0.f, loss = 0.f, cnt = 0.f;
    int   didx = -1;
    float dypre = 0.f;
    float yv[2];
    float ypre = y;
#pragma unroll
    for (int ee = 0; ee < 2; ee++) {
        float ynew = (uh[ee] >= THRES_UP)
                       ? (alv[ee] * uh[ee] + (1.f - alv[ee]) * ypre) : 0.f;
        yv[ee] = ynew;
        if (le[ee] >= THRES1) {
            lcv = (uh[ee] < THRES_UP) ? -1.f : (ynew - le[ee]) * (ynew - le[ee]);
            lcf = 0.f;
        }
        bool fall = (uprev >= THRES_UP) && (ue[ee] < THRES_UP);
        if (fall) {
            if (lcf == 0.f) resolve_fall(lcv, ypre, gbase + ee, th2, loss, cnt);
            else            { didx = gbase + ee; dypre = ypre; }
            lcv = 0.f; lcf = 0.f;
        }
        uprev = ue[ee];
        ypre  = ynew;
    }
    ((float2*)out)[gi] = make_float2(yv[0], yv[1]);

    float fex2, vex2, ft2, vt2;
    blk_scan_excl<2>(lcf, lcv, 0.f, fex2, vex2, ft2, vt2, sf, sv);
    if (didx >= 0 && fex2 == 0.f) {
        resolve_fall(vex2, dypre, didx, th2, loss, cnt);
        didx = -1;
    }
    if (tid == 0) { s_didx = -1; s_dypre = 0.f; }
    __syncthreads();
    if (didx >= 0) { s_didx = didx; s_dypre = dypre; }   // at most one thread
    __syncthreads();

    // block loss/cnt sums
#pragma unroll
    for (int d = 16; d; d >>= 1) {
        loss += __shfl_down_sync(0xffffffffu, loss, d);
        cnt  += __shfl_down_sync(0xffffffffu, cnt,  d);
    }
    if (lane == 0) { sf[w] = loss; sv[w] = cnt; }
    __syncthreads();
    if (tid == 0) {
        float L = 0.f, C = 0.f;
#pragma unroll
        for (int i = 0; i < NW; i++) { L += sf[i]; C += sv[i]; }
        g_D[b] = make_float4(L, C, ft2, vt2);
        g_didx[b]  = s_didx;
        g_dypre[b] = s_dypre;
        st_rel(&g_fD[b], expv);
    }
    __syncthreads();

    // ============ Final resolution: block 0 polls ALL D records ============
    if (b == 0) {
        float L = 0.f, C = 0.f, fl = 1.f, vl = 0.f;
        int   di = -1;
        float dy = 0.f;
        if (tid < NB) {
            while (ld_acq(&g_fD[tid]) != expv) { }
            float4 d4 = g_D[tid];
            L = d4.x; C = d4.y; fl = d4.z; vl = d4.w;
            di = g_didx[tid]; dy = g_dypre[tid];
#pragma unroll
            for (int dd = 1; dd < 32; dd <<= 1) {
                float ff = __shfl_up_sync(0xffffffffu, fl, dd);
                float vv = __shfl_up_sync(0xffffffffu, vl, dd);
                if (lane >= dd) comb<2>(ff, vv, fl, vl);
            }
        }
        __syncthreads();
        if (tid < NB && lane == 31) { sf[w] = fl; sv[w] = vl; }
        __syncthreads();
        if (tid < NB) {
            float pf = 1.f, pv = 0.f;
            for (int i = 0; i < w; i++) {
                float cf = sf[i], cv = sv[i];
                comb<2>(pf, pv, cf, cv);
                pf = cf; pv = cv;
            }
            float lf = __shfl_up_sync(0xffffffffu, fl, 1);
            float lvv = __shfl_up_sync(0xffffffffu, vl, 1);
            if (lane == 0) { lf = 1.f; lvv = 0.f; }
            comb<2>(pf, pv, lf, lvv);
            float lc_in = (lf != 0.f) ? 0.f : lvv;    // initial l_c = 0
            if (di >= 0) resolve_fall(lc_in, dy, di, th2, L, C);
#pragma unroll
            for (int d = 16; d; d >>= 1) {
                L += __shfl_down_sync(0xffffffffu, L, d);
                C += __shfl_down_sync(0xffffffffu, C, d);
            }
        }
        __syncthreads();
        if (tid < NB && lane == 0) { sf[w] = L; sv[w] = C; }
        __syncthreads();
        if (tid == 0 && out_size >= 4 * SEQ + 2) {
            out[4 * SEQ]     = sf[0] + sf[1] + sf[2] + sf[3];
            out[4 * SEQ + 1] = sv[0] + sv[1] + sv[2] + sv[3];
        }
    }

    // ============ Epoch advance (graph-replay safe, no resets) =============
    __syncthreads();
    if (tid == 0) {
        unsigned prev = atomicAdd(&g_done, 1u);
        if (prev == (unsigned)(G - 1)) {
            g_done = 0;
            *(volatile unsigned*)&g_epoch = e + 1u;
        }
    }
}

// ---------------------------------------------------------------------------
extern "C" void kernel_launch(void* const* d_in, const int* in_sizes, int n_in,
                              void* d_out, int out_size) {
    const float* h      = (const float*)d_in[0];
    const float* W      = (const float*)d_in[1];
    const float* bptr   = (const float*)d_in[2];
    // d_in[3] = u (unused in outputs/loss)
    const float* u_pred = (const float*)d_in[4];
    const float* label  = (const float*)d_in[5];
    const float* thres2 = (const float*)d_in[6];
    float* out = (float*)d_out;

    k_tgnn<<<G, TPB>>>(h, W, bptr, u_pred, label, thres2, out, out_size);
}

// round 8
// speedup vs baseline: 1.1059x; 1.1059x over previous
#include <cuda_runtime.h>
#include <math.h>

#define SEQ      65536
#define FEAT     512
#define NB       128          // scan blocks (<=148: all co-resident)
#define TPB      128
#define NW       4
#define THRES1   0.8f
#define THRES_UP 0.5f
#define MAXF     60

__device__ float g_a[SEQ];

// one 128B line per record: flag + payload travel together
struct __align__(128) Slot  { unsigned flag; float f; float v; };
struct __align__(128) SlotD { unsigned flag; float loss, cnt, lf, lv, dypre; int didx; };

__device__ Slot  g_A[NB], g_B[NB], g_C[NB];
__device__ SlotD g_D[NB];
__device__ unsigned g_epoch = 0, g_done = 0;

__device__ __forceinline__ void st_rel(unsigned* p, unsigned v) {
    asm volatile("st.release.gpu.u32 [%0], %1;" :: "l"(p), "r"(v) : "memory");
}
__device__ __forceinline__ unsigned ld_acq(const unsigned* p) {
    unsigned v;
    asm volatile("ld.acquire.gpu.u32 %0, [%1];" : "=r"(v) : "l"(p) : "memory");
    return v;
}
__device__ __forceinline__ void spin_wait(const unsigned* p, unsigned expv) {
    if (ld_acq(p) == expv) return;
    while (ld_acq(p) != expv) __nanosleep(40);
}

// OP 0: segmented max | OP 1: linear | OP 2: last-set select
// comb: t2 := t2 ∘ t1 (t1 earlier, t2 later)
template<int OP>
__device__ __forceinline__ void comb(float f1, float v1, float& f2, float& v2) {
    if (OP == 0) { v2 = (f2 != 0.f) ? fmaxf(v1, v2) : v2; f2 = f1 * f2; }
    if (OP == 1) { v2 = f2 * v1 + v2;                      f2 = f1 * f2; }
    if (OP == 2) { v2 = (f2 != 0.f) ? v1 : v2;             f2 = f1 * f2; }
}

// Block-wide (128 threads) EXCLUSIVE scan; returns exclusive prefix + total.
template<int OP>
__device__ void blk_scan_excl(float f, float v, float idv,
                              float& fex, float& vex,
                              float& ftot, float& vtot,
                              float* sf, float* sv) {
    int lane = threadIdx.x & 31, w = threadIdx.x >> 5;
#pragma unroll
    for (int d = 1; d < 32; d <<= 1) {
        float ff = __shfl_up_sync(0xffffffffu, f, d);
        float vv = __shfl_up_sync(0xffffffffu, v, d);
        if (lane >= d) comb<OP>(ff, vv, f, v);
    }
    __syncthreads();
    if (lane == 31) { sf[w] = f; sv[w] = v; }
    __syncthreads();
    float pf = 1.f, pv = idv;
    for (int i = 0; i < w; i++) {
        float cf = sf[i], cv = sv[i];
        comb<OP>(pf, pv, cf, cv);
        pf = cf; pv = cv;
    }
    float tf = 1.f, tv = idv;
#pragma unroll
    for (int i = 0; i < NW; i++) {
        float cf = sf[i], cv = sv[i];
        comb<OP>(tf, tv, cf, cv);
        tf = cf; tv = cv;
    }
    ftot = tf; vtot = tv;
    float lf = __shfl_up_sync(0xffffffffu, f, 1);
    float lv = __shfl_up_sync(0xffffffffu, v, 1);
    if (lane == 0) { lf = 1.f; lv = idv; }
    comb<OP>(pf, pv, lf, lv);
    fex = lf; vex = lv;
}

// TRUE lookback: thread tid polls record tid ONLY if tid < blockIdx.x.
// Later records contribute identity. tid==blockIdx.x publishes the carry.
template<int OP>
__device__ void lookback_earlier(const Slot* gs, unsigned expv, float idv,
                                 float* sf, float* sv, float* s_c) {
    int tid = threadIdx.x, lane = tid & 31, w = tid >> 5;
    int b = blockIdx.x;
    float f = 1.f, v = idv;
    if (tid < b) {
        spin_wait(&gs[tid].flag, expv);
        f = gs[tid].f; v = gs[tid].v;      // ordered by the acquire above
    }
#pragma unroll
    for (int dd = 1; dd < 32; dd <<= 1) {
        float ff = __shfl_up_sync(0xffffffffu, f, dd);
        float vv = __shfl_up_sync(0xffffffffu, v, dd);
        if (lane >= dd) comb<OP>(ff, vv, f, v);
    }
    __syncthreads();
    if (lane == 31) { sf[w] = f; sv[w] = v; }
    __syncthreads();
    float pf = 1.f, pv = idv;
    for (int i = 0; i < w; i++) {
        float cf = sf[i], cv = sv[i];
        comb<OP>(pf, pv, cf, cv);
        pf = cf; pv = cv;
    }
    float lf = __shfl_up_sync(0xffffffffu, f, 1);
    float lv = __shfl_up_sync(0xffffffffu, v, 1);
    if (lane == 0) { lf = 1.f; lv = idv; }
    comb<OP>(pf, pv, lf, lv);
    if (tid == b) { s_c[0] = lf; s_c[1] = lv; }
    __syncthreads();
}

__device__ __forceinline__ void resolve_fall(float lc, float ypre, int gidx,
                                             const float* __restrict__ th2,
                                             float& loss, float& cnt) {
    bool isneg = (lc == -1.f);
    bool nz    = (lc != 0.f);
    if (!isneg && nz) { loss += lc; cnt += 1.f; }            // * R (R=1)
    else if (!isneg && !nz && ypre >= THRES1) {
        float t2 = th2[gidx < MAXF - 1 ? gidx : MAXF - 1];
        float d = ypre - t2;
        loss += d * d; cnt += 1.f;
    }
}

// ---------------------------------------------------------------------------
// Kernel 1: GEMV + sigmoid, full-chip occupancy (HBM-bound). One warp/row.
// ---------------------------------------------------------------------------
__global__ void __launch_bounds__(256)
gemv_sigmoid_kernel(const float* __restrict__ h,
                    const float* __restrict__ W,
                    const float* __restrict__ b) {
    __shared__ float4 sW[FEAT / 4];
    for (int i = threadIdx.x; i < FEAT / 4; i += blockDim.x)
        sW[i] = ((const float4*)W)[i];
    __syncthreads();

    int row  = (int)((blockIdx.x * blockDim.x + threadIdx.x) >> 5);
    int lane = threadIdx.x & 31;
    const float4* hr = (const float4*)(h + (size_t)row * FEAT);
    float sum = 0.f;
#pragma unroll
    for (int k = 0; k < FEAT / 128; k++) {
        float4 hv = hr[lane + 32 * k];
        float4 wv = sW[lane + 32 * k];
        sum += hv.x * wv.x + hv.y * wv.y + hv.z * wv.z + hv.w * wv.w;
    }
#pragma unroll
    for (int d = 16; d; d >>= 1) sum += __shfl_down_sync(0xffffffffu, sum, d);
    if (lane == 0) g_a[row] = 1.f / (1.f + __expf(-(sum + b[0])));
}

// ---------------------------------------------------------------------------
// Kernel 2: 4 hierarchical scans + loss, padded-flag lookbacks.
// ---------------------------------------------------------------------------
__global__ void __launch_bounds__(TPB, 1)
k_scan_fused(const float* __restrict__ up, const float* __restrict__ lab,
             const float* __restrict__ th2, float* __restrict__ out,
             int out_size) {
    __shared__ float sf[NW], sv[NW];
    __shared__ float s_c[2];
    __shared__ int   s_didx;
    __shared__ float s_dypre;

    const int b    = blockIdx.x;
    const int tid  = threadIdx.x;
    const int lane = tid & 31;
    const int w    = tid >> 5;
    const int gi   = b * TPB + tid;          // float4 index

    const unsigned e    = *(volatile unsigned*)&g_epoch;
    const unsigned expv = e + 1u;

    // ============ Phase A: up_hat (segmented running max) ==================
    float4 u4 = ((const float4*)up)[gi];
    float ue[4] = {u4.x, u4.y, u4.z, u4.w};
    ((float4*)(out + 2 * SEQ))[gi] = u4;     // u_pred copy output

    float f = 1.f, v = -1.f;
#pragma unroll
    for (int ee = 0; ee < 4; ee++) {
        if (ue[ee] >= THRES_UP) v = fmaxf(v, ue[ee]);
        else { f = 0.f; v = -1.f; }
    }
    float fexA, vexA, ftA, vtA;
    blk_scan_excl<0>(f, v, -1.f, fexA, vexA, ftA, vtA, sf, sv);
    if (tid == 0) {
        g_A[b].f = ftA; g_A[b].v = vtA;
        st_rel(&g_A[b].flag, expv);
    }
    lookback_earlier<0>(g_A, expv, -1.f, sf, sv, s_c);
    float m = (fexA != 0.f) ? fmaxf(s_c[1], vexA) : vexA;

    float uh[4];
#pragma unroll
    for (int ee = 0; ee < 4; ee++) {
        if (ue[ee] >= THRES_UP) { m = fmaxf(m, ue[ee]); uh[ee] = m; }
        else                    { m = -1.f;             uh[ee] = ue[ee]; }
    }
    ((float4*)(out + 3 * SEQ))[gi] = make_float4(uh[0], uh[1], uh[2], uh[3]);

    // ============ Phase B: alpha (linear scan) ==============================
    float4 a4 = ((const float4*)g_a)[gi];
    float ae[4] = {a4.x, a4.y, a4.z, a4.w};
    float p = 1.f, q = 0.f;
#pragma unroll
    for (int ee = 0; ee < 4; ee++) {
        q = uh[ee] * q + (1.f - uh[ee]) * ae[ee];
        p = uh[ee] * p;
    }
    float fexB, vexB, ftB, vtB;
    blk_scan_excl<1>(p, q, 0.f, fexB, vexB, ftB, vtB, sf, sv);
    if (tid == 0) {
        g_B[b].f = ftB; g_B[b].v = vtB;
        st_rel(&g_B[b].flag, expv);
    }
    lookback_earlier<1>(g_B, expv, 0.f, sf, sv, s_c);
    float al = fexB * s_c[1] + vexB;

    float alv[4];
#pragma unroll
    for (int ee = 0; ee < 4; ee++) {
        al = uh[ee] * al + (1.f - uh[ee]) * ae[ee];
        alv[ee] = al;
    }
    ((float4*)(out + SEQ))[gi] = make_float4(alv[0], alv[1], alv[2], alv[3]);

    // ============ Phase C: y (linear scan with resets) ======================
    float yp = 1.f, yq = 0.f;
#pragma unroll
    for (int ee = 0; ee < 4; ee++) {
        float A = 0.f, B = 0.f;
        if (uh[ee] >= THRES_UP) { A = 1.f - alv[ee]; B = alv[ee] * uh[ee]; }
        yq = A * yq + B;
        yp = A * yp;
    }
    float fexC, vexC, ftC, vtC;
    blk_scan_excl<1>(yp, yq, 0.f, fexC, vexC, ftC, vtC, sf, sv);
    if (tid == 0) {
        g_C[b].f = ftC; g_C[b].v = vtC;
        st_rel(&g_C[b].flag, expv);
    }
    lookback_earlier<1>(g_C, expv, 0.f, sf, sv, s_c);
    float y = fexC * s_c[1] + vexC;          // y entering this thread's chunk

    // ============ Phase D: y values + l_c / loss / cnt ======================
    float4 l4 = ((const float4*)lab)[gi];
    float le[4] = {l4.x, l4.y, l4.z, l4.w};

    int   gbase = gi * 4;
    float uprev = (gbase == 0) ? 0.f : up[gbase - 1];

    float lcf = 1.f, lcv = 0.f, loss = 0.f, cnt = 0.f;
    int   didx = -1;
    float dypre = 0.f;
    float yv[4];
    float ypre = y;
#pragma unroll
    for (int ee = 0; ee < 4; ee++) {
        float ynew = (uh[ee] >= THRES_UP)
                       ? (alv[ee] * uh[ee] + (1.f - alv[ee]) * ypre) : 0.f;
        yv[ee] = ynew;
        if (le[ee] >= THRES1) {
            lcv = (uh[ee] < THRES_UP) ? -1.f : (ynew - le[ee]) * (ynew - le[ee]);
            lcf = 0.f;
        }
        bool fall = (uprev >= THRES_UP) && (ue[ee] < THRES_UP);
        if (fall) {
            if (lcf == 0.f) resolve_fall(lcv, ypre, gbase + ee, th2, loss, cnt);
            else            { didx = gbase + ee; dypre = ypre; }
            lcv = 0.f; lcf = 0.f;
        }
        uprev = ue[ee];
        ypre  = ynew;
    }
    ((float4*)out)[gi] = make_float4(yv[0], yv[1], yv[2], yv[3]);

    // in-block l_c scan; resolve thread defers whose prefix is known
    float fex2, vex2, ft2, vt2;
    blk_scan_excl<2>(lcf, lcv, 0.f, fex2, vex2, ft2, vt2, sf, sv);
    if (didx >= 0 && fex2 == 0.f) {
        resolve_fall(vex2, dypre, didx, th2, loss, cnt);
        didx = -1;
    }
    if (tid == 0) { s_didx = -1; s_dypre = 0.f; }
    __syncthreads();
    if (didx >= 0) { s_didx = didx; s_dypre = dypre; }   // at most one thread
    __syncthreads();

    // block loss/cnt sums
#pragma unroll
    for (int d = 16; d; d >>= 1) {
        loss += __shfl_down_sync(0xffffffffu, loss, d);
        cnt  += __shfl_down_sync(0xffffffffu, cnt,  d);
    }
    if (lane == 0) { sf[w] = loss; sv[w] = cnt; }
    __syncthreads();
    if (tid == 0) {
        SlotD* d = &g_D[b];
        d->loss  = sf[0] + sf[1] + sf[2] + sf[3];
        d->cnt   = sv[0] + sv[1] + sv[2] + sv[3];
        d->lf    = ft2;
        d->lv    = vt2;
        d->didx  = s_didx;
        d->dypre = s_dypre;
        st_rel(&d->flag, expv);
    }
    __syncthreads();

    // ============ Final resolution: block 0 polls ALL D records ============
    if (b == 0) {
        spin_wait(&g_D[tid].flag, expv);
        SlotD* d = &g_D[tid];
        float L = d->loss, C = d->cnt, fl = d->lf, vl = d->lv;
        int   di = d->didx;
        float dy = d->dypre;
#pragma unroll
        for (int dd = 1; dd < 32; dd <<= 1) {
            float ff = __shfl_up_sync(0xffffffffu, fl, dd);
            float vv = __shfl_up_sync(0xffffffffu, vl, dd);
            if (lane >= dd) comb<2>(ff, vv, fl, vl);
        }
        __syncthreads();
        if (lane == 31) { sf[w] = fl; sv[w] = vl; }
        __syncthreads();
        float pf = 1.f, pv = 0.f;
        for (int i = 0; i < w; i++) {
            float cf = sf[i], cv = sv[i];
            comb<2>(pf, pv, cf, cv);
            pf = cf; pv = cv;
        }
        float lf = __shfl_up_sync(0xffffffffu, fl, 1);
        float lvv = __shfl_up_sync(0xffffffffu, vl, 1);
        if (lane == 0) { lf = 1.f; lvv = 0.f; }
        comb<2>(pf, pv, lf, lvv);
        float lc_in = (lf != 0.f) ? 0.f : lvv;        // initial l_c = 0
        if (di >= 0) resolve_fall(lc_in, dy, di, th2, L, C);
#pragma unroll
        for (int d2 = 16; d2; d2 >>= 1) {
            L += __shfl_down_sync(0xffffffffu, L, d2);
            C += __shfl_down_sync(0xffffffffu, C, d2);
        }
        __syncthreads();
        if (lane == 0) { sf[w] = L; sv[w] = C; }
        __syncthreads();
        if (tid == 0 && out_size >= 4 * SEQ + 2) {
            out[4 * SEQ]     = sf[0] + sf[1] + sf[2] + sf[3];
            out[4 * SEQ + 1] = sv[0] + sv[1] + sv[2] + sv[3];
        }
    }

    // ============ Epoch advance (graph-replay safe, no resets) =============
    __syncthreads();
    if (tid == 0) {
        unsigned prev = atomicAdd(&g_done, 1u);
        if (prev == (unsigned)(NB - 1)) {
            g_done = 0;
            *(volatile unsigned*)&g_epoch = e + 1u;
        }
    }
}

// ---------------------------------------------------------------------------
extern "C" void kernel_launch(void* const* d_in, const int* in_sizes, int n_in,
                              void* d_out, int out_size) {
    const float* h      = (const float*)d_in[0];
    const float* W      = (const float*)d_in[1];
    const float* bptr   = (const float*)d_in[2];
    // d_in[3] = u (unused in outputs/loss)
    const float* u_pred = (const float*)d_in[4];
    const float* label  = (const float*)d_in[5];
    const float* thres2 = (const float*)d_in[6];
    float* out = (float*)d_out;

    gemv_sigmoid_kernel<<<SEQ / 8, 256>>>(h, W, bptr);
    k_scan_fused<<<NB, TPB>>>(u_pred, label, thres2, out, out_size);
}